// round 14
// baseline (speedup 1.0000x reference)
#include <cuda_runtime.h>
#include <cuda_bf16.h>
#include <cstdint>
#include <math.h>

#define BB 16
#define LL 2048
#define DIN 64
#define HH 256
#define NH 32
#define NLAYERS 4
#define DM1 128
#define DM2 64
#define DOUT 32

#define MROWS (BB*LL)          // 32768
#define NMBLK (MROWS/128)      // 256 row blocks

#define NCHUNK 16
#define CLEN (LL/NCHUNK)       // 128

typedef unsigned long long u64;

// Scratch (allocation-free contract: __device__ globals)
__device__ float g_zr [MROWS*HH];                // layer activations (pre-LN)
__device__ float2 g_lnstat[MROWS];               // per-row (mean, rstd)
// A fragments (bf16 pairs): [mblock(256)][kchunk(8)][ks(2)][mtile(8)][lane(32)][reg(4)]
__device__ __align__(16) uint32_t g_af_hi[(size_t)NMBLK*16384];
__device__ __align__(16) uint32_t g_af_lo[(size_t)NMBLK*16384];
// B fragments interleaved (hi0,lo0,hi1,lo1 per (nt,lane)):
__device__ __align__(16) uint32_t g_wf[(size_t)NLAYERS*4*32768];
// scan coefficient tables (packed f32 pairs as u64)
//   ctab[(layer*HH+ch)*16 + n2][4] = {wre2, wim2, ckre2, nckim2}
__device__ __align__(16) u64 g_ctab[(size_t)NLAYERS*HH*16*4];
//   wptab[(layer*HH+ch)*16 + n2][2] = {wpr2, wpi2}   (w^CLEN)
__device__ __align__(16) u64 g_wptab[(size_t)NLAYERS*HH*16*2];
// packed carries: [chunk][b][ch][j(8)][4] = {re2_g0, im2_g0, re2_g1, im2_g1}
__device__ __align__(16) u64 g_carryp[(size_t)NCHUNK*BB*HH*8*4];
__device__ float g_poolp[BB*16*HH];

// ---------------------------------------------------------------------------
// helpers
// ---------------------------------------------------------------------------
__device__ __forceinline__ uint32_t smem_u32(const void* p) {
    uint32_t a;
    asm("{ .reg .u64 t; cvta.to.shared.u64 t, %1; cvt.u32.u64 %0, t; }"
        : "=r"(a) : "l"(p));
    return a;
}
__device__ __forceinline__ unsigned short bfu(float x) {
    return __bfloat16_as_ushort(__float2bfloat16_rn(x));
}
__device__ __forceinline__ float bff(unsigned short u) {
    return __bfloat162float(__ushort_as_bfloat16(u));
}
__device__ __forceinline__ void cp16(uint32_t dst, const void* src) {
    asm volatile("cp.async.cg.shared.global [%0], [%1], 16;"
                 :: "r"(dst), "l"(src));
}
__device__ __forceinline__ void mma_bf16(float* d, const uint32_t* a,
                                         uint32_t b0, uint32_t b1) {
    asm volatile(
        "mma.sync.aligned.m16n8k16.row.col.f32.bf16.bf16.f32 "
        "{%0,%1,%2,%3}, {%4,%5,%6,%7}, {%8,%9}, {%0,%1,%2,%3};"
        : "+f"(d[0]), "+f"(d[1]), "+f"(d[2]), "+f"(d[3])
        : "r"(a[0]), "r"(a[1]), "r"(a[2]), "r"(a[3]), "r"(b0), "r"(b1));
}
__device__ __forceinline__ u64 pk2(float lo, float hi) {
    u64 r; asm("mov.b64 %0, {%1, %2};" : "=l"(r) : "f"(lo), "f"(hi)); return r;
}
__device__ __forceinline__ void upk2(float& lo, float& hi, u64 v) {
    asm("mov.b64 {%0, %1}, %2;" : "=f"(lo), "=f"(hi) : "l"(v));
}
__device__ __forceinline__ u64 fma2(u64 a, u64 b, u64 c) {
    u64 d; asm("fma.rn.f32x2 %0, %1, %2, %3;" : "=l"(d) : "l"(a), "l"(b), "l"(c));
    return d;
}
#define NEG2(x) ((x) ^ 0x8000000080000000ull)

// ---------------------------------------------------------------------------
// Coefficient table prep: one thread per (layer, ch, n2) covering 2 states.
// ---------------------------------------------------------------------------
__global__ __launch_bounds__(128) void prep_ctab_kernel(
        const float* __restrict__ log_dt, const float* __restrict__ C_re,
        const float* __restrict__ C_im,   const float* __restrict__ log_A_real,
        const float* __restrict__ A_imag) {
    int i = blockIdx.x * 128 + threadIdx.x;      // (layer*HH+ch)*16 + n2
    if (i >= NLAYERS * HH * 16) return;
    int lc = i >> 4;                             // layer*HH + ch
    int n2 = i & 15;
    float dt = expf(log_dt[lc]);
    float wre[2], wim[2], cr[2], ci[2], wpr[2], wpi[2];
    #pragma unroll
    for (int e = 0; e < 2; e++) {
        int idx = lc * NH + n2 * 2 + e;
        float Are = -expf(log_A_real[idx]);
        float Aim = A_imag[idx];
        float er  = expf(dt * Are);
        wre[e] = er * cosf(dt * Aim);
        wim[e] = er * sinf(dt * Aim);
        float nre = wre[e] - 1.0f, nim = wim[e];
        float inv = 1.0f / (Are * Are + Aim * Aim);
        float ire = Are * inv, iim = -Aim * inv;
        float tre = nre * ire - nim * iim;
        float tim = nre * iim + nim * ire;
        float cre = C_re[idx], cim = C_im[idx];
        cr[e] = 2.0f * (cre * tre - cim * tim);
        ci[e] = 2.0f * (cre * tim + cim * tre);
        float erp  = expf((float)CLEN * dt * Are);
        float angp = (float)CLEN * dt * Aim;
        wpr[e] = erp * cosf(angp);
        wpi[e] = erp * sinf(angp);
    }
    u64* cp = &g_ctab[(size_t)i * 4];
    cp[0] = pk2(wre[0], wre[1]);
    cp[1] = pk2(wim[0], wim[1]);
    cp[2] = pk2(cr[0], cr[1]);
    cp[3] = pk2(-ci[0], -ci[1]);
    u64* wp = &g_wptab[(size_t)i * 2];
    wp[0] = pk2(wpr[0], wpr[1]);
    wp[1] = pk2(wpi[0], wpi[1]);
}

// ---------------------------------------------------------------------------
// Weight prep: bf16x3 split of w_out into interleaved fragment order.
// ---------------------------------------------------------------------------
__global__ __launch_bounds__(256) void prep_w_kernel(const float* __restrict__ w) {
    int i = blockIdx.x * 256 + threadIdx.x;
    if (i >= NLAYERS * 512 * 128) return;
    int hp = i & 127;          int h = hp * 2;
    int o  = (i >> 7) & 511;
    int layer = i >> 16;
    float v0 = w[((size_t)(layer * 512) + o) * 256 + h];
    float v1 = w[((size_t)(layer * 512) + o) * 256 + h + 1];
    unsigned short h0 = bfu(v0), h1 = bfu(v1);
    unsigned short l0 = bfu(v0 - bff(h0)), l1 = bfu(v1 - bff(h1));
    int half = o >> 8;
    int nb   = (o & 255) >> 6;
    int nt   = ((o >> 3) & 7) | (half << 3);
    int gid  = o & 7;
    int kchunk = h >> 5;
    int ks   = (h >> 4) & 1;
    int kk   = h & 15;
    int tig  = (kk & 7) >> 1;
    int reg  = kk >> 3;
    int lane = gid * 4 + tig;
    size_t idx = ((((((size_t)(layer * 4 + nb) * 8 + kchunk) * 2 + ks) * 16 + nt) * 32 + lane) * 2 + reg) * 2;
    g_wf[idx]     = (uint32_t)h0 | ((uint32_t)h1 << 16);
    g_wf[idx + 1] = (uint32_t)l0 | ((uint32_t)l1 << 16);
}

// ---------------------------------------------------------------------------
// Encoder: g_zr[m, n] = x[m, :64] @ enc_w[:, n] + enc_b[n]
// ---------------------------------------------------------------------------
__global__ __launch_bounds__(256) void encoder_kernel(
        const float* __restrict__ X, const float* __restrict__ W,
        const float* __restrict__ bias) {
    __shared__ float As[64][36];
    __shared__ float Bs[32][68];
    int row0 = blockIdx.x * 64;
    int n0   = blockIdx.y * 64;
    int tid = threadIdx.x;
    int tx = tid & 15, ty = tid >> 4;
    float acc[4][4] = {};
    for (int k0 = 0; k0 < DIN; k0 += 32) {
        #pragma unroll
        for (int p = 0; p < 2; p++) {
            int q = tid + p * 256;
            int r = q >> 3, kq = q & 7;
            float4 v = *(const float4*)&X[(row0 + r) * DIN + k0 + kq * 4];
            *(float4*)&As[r][kq * 4] = v;
        }
        #pragma unroll
        for (int p = 0; p < 2; p++) {
            int q = tid + p * 256;
            int kk = q >> 4, nq = q & 15;
            float4 v = *(const float4*)&W[(k0 + kk) * HH + n0 + nq * 4];
            *(float4*)&Bs[kk][nq * 4] = v;
        }
        __syncthreads();
        #pragma unroll
        for (int k = 0; k < 32; k++) {
            float a[4];
            #pragma unroll
            for (int i = 0; i < 4; i++) a[i] = As[ty * 4 + i][k];
            float4 bv = *(const float4*)&Bs[k][tx * 4];
            float bj[4] = {bv.x, bv.y, bv.z, bv.w};
            #pragma unroll
            for (int i = 0; i < 4; i++)
                #pragma unroll
                for (int j = 0; j < 4; j++)
                    acc[i][j] = fmaf(a[i], bj[j], acc[i][j]);
        }
        __syncthreads();
    }
    #pragma unroll
    for (int i = 0; i < 4; i++) {
        int m = row0 + ty * 4 + i;
        #pragma unroll
        for (int j = 0; j < 4; j++) {
            int n = n0 + tx * 4 + j;
            g_zr[m * HH + n] = acc[i][j] + bias[n];
        }
    }
}

// ---------------------------------------------------------------------------
// LN stats: per-row mean/rstd of g_zr.  One warp per row.
// ---------------------------------------------------------------------------
__global__ __launch_bounds__(256) void lnstat_kernel() {
    int row  = blockIdx.x * 8 + (threadIdx.x >> 5);
    int lane = threadIdx.x & 31;
    const float* Z = g_zr + (size_t)row * HH;
    float4 v0 = *(const float4*)&Z[lane * 4];
    float4 v1 = *(const float4*)&Z[128 + lane * 4];
    float s  = v0.x + v0.y + v0.z + v0.w + v1.x + v1.y + v1.z + v1.w;
    float ss = v0.x*v0.x + v0.y*v0.y + v0.z*v0.z + v0.w*v0.w
             + v1.x*v1.x + v1.y*v1.y + v1.z*v1.z + v1.w*v1.w;
    #pragma unroll
    for (int o = 16; o; o >>= 1) {
        s  += __shfl_xor_sync(0xffffffffu, s,  o);
        ss += __shfl_xor_sync(0xffffffffu, ss, o);
    }
    float mean = s * (1.0f / 256.0f);
    float var  = ss * (1.0f / 256.0f) - mean * mean;
    if (lane == 0)
        g_lnstat[row] = make_float2(mean, rsqrtf(var + 1e-5f));
}

// ---------------------------------------------------------------------------
// Scan phase 1: per-chunk local recurrence from zero state; packed carry out.
// grid (B, H/16, NCHUNK-1), block 128.
// ---------------------------------------------------------------------------
__global__ __launch_bounds__(128, 12) void scan_p1(
        const float* __restrict__ lng_p, const float* __restrict__ lnb_p,
        int apply_ln, int layer) {
    __shared__ float s_in[128 * 16];
    int b   = blockIdx.x;
    int ch0 = blockIdx.y * 16;
    int chunk = blockIdx.z;
    int tid = threadIdx.x;
    int warp = tid >> 5, lane = tid & 31;
    int g = lane >> 3, j = lane & 7;
    int c_local = warp * 4 + g;
    int ch = ch0 + c_local;

    u64 wre2[2], nwim2[2], wim2[2], sre2[2], sim2[2];
    {
        size_t cb = ((size_t)(layer * HH + ch) * 16 + j * 2) * 4;
        #pragma unroll
        for (int g2 = 0; g2 < 2; g2++) {
            ulonglong2 p0 = *(const ulonglong2*)&g_ctab[cb + g2 * 4];
            wre2[g2] = p0.x; wim2[g2] = p0.y;
            nwim2[g2] = NEG2(p0.y);
            sre2[g2] = 0ull; sim2[g2] = 0ull;
        }
    }

    size_t base_m = (size_t)b * LL + (size_t)chunk * CLEN;
    const float* hin = g_zr + base_m * HH;
    const float2* stp = g_lnstat + base_m;
    #pragma unroll
    for (int p = 0; p < 4; p++) {
        int q = tid + p * 128;
        int t = q >> 2, cq = q & 3;
        float4 v = *(const float4*)&hin[t * HH + ch0 + cq * 4];
        if (apply_ln) {
            float2 st = stp[t];
            float4 gg = *(const float4*)&lng_p[ch0 + cq * 4];
            float4 bb = *(const float4*)&lnb_p[ch0 + cq * 4];
            v.x = (v.x - st.x) * st.y * gg.x + bb.x;
            v.y = (v.y - st.x) * st.y * gg.y + bb.y;
            v.z = (v.z - st.x) * st.y * gg.z + bb.z;
            v.w = (v.w - st.x) * st.y * gg.w + bb.w;
        }
        *(float4*)&s_in[t * 16 + cq * 4] = v;
    }
    __syncthreads();
    #pragma unroll 8
    for (int t = 0; t < CLEN; t++) {
        float u = s_in[t * 16 + c_local];
        u64 u2 = pk2(u, u);
        #pragma unroll
        for (int g2 = 0; g2 < 2; g2++) {
            u64 nr = fma2(wre2[g2], sre2[g2], u2);
            nr = fma2(nwim2[g2], sim2[g2], nr);
            u64 ni = fma2(wre2[g2], sim2[g2], 0ull);
            ni = fma2(wim2[g2], sre2[g2], ni);
            sre2[g2] = nr; sim2[g2] = ni;
        }
    }
    size_t cpb = (((size_t)(chunk * BB + b) * HH + ch) * 8 + j) * 4;
    *(ulonglong2*)&g_carryp[cpb]     = make_ulonglong2(sre2[0], sim2[0]);
    *(ulonglong2*)&g_carryp[cpb + 2] = make_ulonglong2(sre2[1], sim2[1]);
}

// ---------------------------------------------------------------------------
// Scan phase 2: packed Horner carry combine + per-chunk scan + D-skip + GELU
// + bf16x3 fragment emission.  grid (B, H/16, NCHUNK), block 128.
// ---------------------------------------------------------------------------
__global__ __launch_bounds__(128, 12) void scan_p2(
        const float* __restrict__ D_skip,
        const float* __restrict__ lng_p, const float* __restrict__ lnb_p,
        int apply_ln, int layer) {
    __shared__ float s_buf[128 * 16];        // 8KB: input tile / scan output
    __shared__ uint32_t s_frag[2048];        // 8KB: hi (1024) | lo (1024)
    int b   = blockIdx.x;
    int ch0 = blockIdx.y * 16;
    int chunk = blockIdx.z;
    int tid = threadIdx.x;
    int warp = tid >> 5, lane = tid & 31;
    int g = lane >> 3, j = lane & 7;
    int c_local = warp * 4 + g;
    int ch = ch0 + c_local;

    float dsk = D_skip[layer * HH + ch];
    u64 wre2[2], wim2[2], nwim2[2], ckre2[2], nckim2[2], sre2[2], sim2[2];
    {
        size_t cb = ((size_t)(layer * HH + ch) * 16 + j * 2) * 4;
        #pragma unroll
        for (int g2 = 0; g2 < 2; g2++) {
            ulonglong2 p0 = *(const ulonglong2*)&g_ctab[cb + g2 * 4];
            ulonglong2 p1 = *(const ulonglong2*)&g_ctab[cb + g2 * 4 + 2];
            wre2[g2] = p0.x; wim2[g2] = p0.y; nwim2[g2] = NEG2(p0.y);
            ckre2[g2] = p1.x; nckim2[g2] = p1.y;
            sre2[g2] = 0ull; sim2[g2] = 0ull;
        }
    }
    // Horner combine over preceding chunk end-states (packed fma2)
    if (chunk > 0) {
        size_t wb = ((size_t)(layer * HH + ch) * 16 + j * 2) * 2;
        u64 wpr2[2], wpi2[2], nwpi2[2];
        #pragma unroll
        for (int g2 = 0; g2 < 2; g2++) {
            ulonglong2 wv = *(const ulonglong2*)&g_wptab[wb + g2 * 2];
            wpr2[g2] = wv.x; wpi2[g2] = wv.y; nwpi2[g2] = NEG2(wv.y);
        }
        for (int c = 0; c < chunk; c++) {
            size_t cpb = (((size_t)(c * BB + b) * HH + ch) * 8 + j) * 4;
            ulonglong2 e0 = *(const ulonglong2*)&g_carryp[cpb];
            ulonglong2 e1 = *(const ulonglong2*)&g_carryp[cpb + 2];
            u64 er[2] = {e0.x, e1.x}, ei[2] = {e0.y, e1.y};
            #pragma unroll
            for (int g2 = 0; g2 < 2; g2++) {
                u64 nr = fma2(wpr2[g2], sre2[g2], er[g2]);
                nr = fma2(nwpi2[g2], sim2[g2], nr);
                u64 ni = fma2(wpr2[g2], sim2[g2], ei[g2]);
                ni = fma2(wpi2[g2], sre2[g2], ni);
                sre2[g2] = nr; sim2[g2] = ni;
            }
        }
    }

    size_t base_m = (size_t)b * LL + (size_t)chunk * CLEN;
    const float* hin = g_zr + base_m * HH;
    const float2* stp = g_lnstat + base_m;

    #pragma unroll
    for (int p = 0; p < 4; p++) {
        int q = tid + p * 128;
        int t = q >> 2, cq = q & 3;
        float4 v = *(const float4*)&hin[t * HH + ch0 + cq * 4];
        if (apply_ln) {
            float2 st = stp[t];
            float4 gg = *(const float4*)&lng_p[ch0 + cq * 4];
            float4 bb = *(const float4*)&lnb_p[ch0 + cq * 4];
            v.x = (v.x - st.x) * st.y * gg.x + bb.x;
            v.y = (v.y - st.x) * st.y * gg.y + bb.y;
            v.z = (v.z - st.x) * st.y * gg.z + bb.z;
            v.w = (v.w - st.x) * st.y * gg.w + bb.w;
        }
        *(float4*)&s_buf[t * 16 + cq * 4] = v;
    }
    __syncthreads();
    // scan; lane j==0 writes output IN PLACE (warp-synchronous safe)
    #pragma unroll 8
    for (int t = 0; t < CLEN; t++) {
        float u = s_buf[t * 16 + c_local];
        u64 u2 = pk2(u, u);
        u64 pacc2 = 0ull;
        #pragma unroll
        for (int g2 = 0; g2 < 2; g2++) {
            u64 nr = fma2(wre2[g2], sre2[g2], u2);
            nr = fma2(nwim2[g2], sim2[g2], nr);
            u64 ni = fma2(wre2[g2], sim2[g2], 0ull);
            ni = fma2(wim2[g2], sre2[g2], ni);
            sre2[g2] = nr; sim2[g2] = ni;
            pacc2 = fma2(ckre2[g2], nr, pacc2);
            pacc2 = fma2(nckim2[g2], ni, pacc2);
        }
        float pa, pb;
        upk2(pa, pb, pacc2);
        float pacc = pa + pb;
        pacc += __shfl_xor_sync(0xffffffffu, pacc, 1);
        pacc += __shfl_xor_sync(0xffffffffu, pacc, 2);
        pacc += __shfl_xor_sync(0xffffffffu, pacc, 4);
        if (j == 0)
            s_buf[t * 16 + c_local] = fmaf(u, dsk, pacc);
    }
    __syncthreads();
    // GELU + bf16x3 split -> fragment buffer
    uint32_t* s_fh = s_frag;
    uint32_t* s_fl = s_frag + 1024;
    #pragma unroll
    for (int p = 0; p < 4; p++) {
        int q = tid + p * 128;
        int t = q >> 2, cq = q & 3;
        float4 v = *(const float4*)&s_buf[t * 16 + cq * 4];
        v.x = 0.5f * v.x * (1.0f + erff(v.x * 0.70710678118654752f));
        v.y = 0.5f * v.y * (1.0f + erff(v.y * 0.70710678118654752f));
        v.z = 0.5f * v.z * (1.0f + erff(v.z * 0.70710678118654752f));
        v.w = 0.5f * v.w * (1.0f + erff(v.w * 0.70710678118654752f));
        int mtile  = t >> 4;
        int rowsel = (t >> 3) & 1;
        int gid    = t & 7;
        int kk     = cq * 4;
        int tig0   = (kk & 7) >> 1;
        int reg    = rowsel + ((kk >> 3) << 1);
        int base   = (mtile * 32 + gid * 4 + tig0) * 4 + reg;
        unsigned short hx = bfu(v.x), hy = bfu(v.y), hz = bfu(v.z), hw = bfu(v.w);
        unsigned short lx = bfu(v.x - bff(hx)), ly = bfu(v.y - bff(hy));
        unsigned short lz = bfu(v.z - bff(hz)), lw = bfu(v.w - bff(hw));
        s_fh[base]     = (uint32_t)hx | ((uint32_t)hy << 16);
        s_fh[base + 4] = (uint32_t)hz | ((uint32_t)hw << 16);
        s_fl[base]     = (uint32_t)lx | ((uint32_t)ly << 16);
        s_fl[base + 4] = (uint32_t)lz | ((uint32_t)lw << 16);
    }
    __syncthreads();
    int mblk   = (int)(base_m >> 7);
    int kchunk = ch0 >> 5;
    int ks     = (ch0 >> 4) & 1;
    size_t gb = (size_t)mblk * 16384 + (size_t)(kchunk * 2 + ks) * 1024;
    #pragma unroll
    for (int p = 0; p < 2; p++) {
        int i = (tid + p * 128) * 4;
        *(uint4*)&g_af_hi[gb + i] = *(const uint4*)&s_fh[i];
        *(uint4*)&g_af_lo[gb + i] = *(const uint4*)&s_fl[i];
    }
}

// ---------------------------------------------------------------------------
// bf16x3 warp-MMA GEMM (interleaved B), register-GLU epilogue with inline LN,
// 3-stage cp.async pipeline.  Writes zr in place.  (unchanged from R13)
// ---------------------------------------------------------------------------
#define GEMM_SMEM 98304
__global__ __launch_bounds__(256, 2) void gemm_glu_tc(
        const float* __restrict__ bias_all,
        const float* __restrict__ lng_p, const float* __restrict__ lnb_p,
        int apply_ln, int layer) {
    extern __shared__ uint32_t sm[];
    int tid = threadIdx.x, lane = tid & 31, wid = tid >> 5;
    int wm = wid & 3, wn = wid >> 2;
    int mb = blockIdx.x, nb = blockIdx.y;
    uint32_t sbase = smem_u32(sm);

    const uint32_t* Ah = g_af_hi + (size_t)mb * 16384;
    const uint32_t* Al = g_af_lo + (size_t)mb * 16384;
    const uint32_t* Bi = g_wf + (size_t)(layer * 4 + nb) * 32768;

    float acca[2][4][4] = {};
    float accg[2][4][4] = {};

    #pragma unroll
    for (int st = 0; st < 3; st++) {
        uint32_t db = sbase + st * 32768u;
        #pragma unroll
        for (int ii = 0; ii < 2; ii++) {
            int c = tid + ii * 256;
            cp16(db +         c * 16, Ah + (size_t)st * 2048 + c * 4);
            cp16(db + 8192u + c * 16, Al + (size_t)st * 2048 + c * 4);
        }
        #pragma unroll
        for (int ii = 0; ii < 4; ii++) {
            int c = tid + ii * 256;
            cp16(db + 16384u + c * 16, Bi + (size_t)st * 4096 + c * 4);
        }
        asm volatile("cp.async.commit_group;");
    }

    for (int kc = 0; kc < 8; kc++) {
        asm volatile("cp.async.wait_group 2;");
        __syncthreads();
        int stg = kc % 3;
        const uint32_t* sAh = sm + stg * 8192;
        const uint32_t* sAl = sAh + 2048;
        const uint32_t* sB  = sAh + 4096;
        #pragma unroll
        for (int ks = 0; ks < 2; ks++) {
            uint32_t ah[2][4], al[2][4];
            #pragma unroll
            for (int mt = 0; mt < 2; mt++) {
                int base = (ks * 8 + wm * 2 + mt) * 128 + lane * 4;
                uint4 qh = *(const uint4*)&sAh[base];
                uint4 ql = *(const uint4*)&sAl[base];
                ah[mt][0] = qh.x; ah[mt][1] = qh.y; ah[mt][2] = qh.z; ah[mt][3] = qh.w;
                al[mt][0] = ql.x; al[mt][1] = ql.y; al[mt][2] = ql.z; al[mt][3] = ql.w;
            }
            #pragma unroll
            for (int i = 0; i < 4; i++) {
                int bidx_a = ((ks * 16 +     wn * 4 + i) * 32 + lane) * 4;
                int bidx_g = ((ks * 16 + 8 + wn * 4 + i) * 32 + lane) * 4;
                uint4 qa = *(const uint4*)&sB[bidx_a];   // hi0,lo0,hi1,lo1
                uint4 qg = *(const uint4*)&sB[bidx_g];
                #pragma unroll
                for (int mt = 0; mt < 2; mt++) {
                    mma_bf16(acca[mt][i], ah[mt], qa.x, qa.z);
                    mma_bf16(acca[mt][i], al[mt], qa.x, qa.z);
                    mma_bf16(acca[mt][i], ah[mt], qa.y, qa.w);
                    mma_bf16(accg[mt][i], ah[mt], qg.x, qg.z);
                    mma_bf16(accg[mt][i], al[mt], qg.x, qg.z);
                    mma_bf16(accg[mt][i], ah[mt], qg.y, qg.w);
                }
            }
        }
        __syncthreads();
        if (kc < 5) {
            int st = kc + 3;
            uint32_t db = sbase + (st % 3) * 32768u;
            #pragma unroll
            for (int ii = 0; ii < 2; ii++) {
                int c = tid + ii * 256;
                cp16(db +         c * 16, Ah + (size_t)st * 2048 + c * 4);
                cp16(db + 8192u + c * 16, Al + (size_t)st * 2048 + c * 4);
            }
            #pragma unroll
            for (int ii = 0; ii < 4; ii++) {
                int c = tid + ii * 256;
                cp16(db + 16384u + c * 16, Bi + (size_t)st * 4096 + c * 4);
            }
            asm volatile("cp.async.commit_group;");
        } else {
            asm volatile("cp.async.commit_group;");
        }
    }

    // register epilogue: bias + GLU + residual(LN'd) -> g_zr (in place)
    const float* brow = bias_all + layer * 512;
    #pragma unroll
    for (int i = 0; i < 4; i++) {
        int cbase = nb * 64 + wn * 32 + i * 8 + (lane & 3) * 2;
        float ba0 = brow[cbase],       ba1 = brow[cbase + 1];
        float bg0 = brow[cbase + 256], bg1 = brow[cbase + 257];
        float ga0 = 1.f, ga1 = 1.f, be0 = 0.f, be1 = 0.f;
        if (apply_ln) {
            ga0 = lng_p[cbase]; ga1 = lng_p[cbase + 1];
            be0 = lnb_p[cbase]; be1 = lnb_p[cbase + 1];
        }
        #pragma unroll
        for (int mt = 0; mt < 2; mt++) {
            int r0 = mb * 128 + wm * 32 + mt * 16 + (lane >> 2);
            #pragma unroll
            for (int half = 0; half < 2; half++) {
                size_t m = (size_t)r0 + half * 8;
                float a0 = acca[mt][i][half * 2 + 0] + ba0;
                float a1 = acca[mt][i][half * 2 + 1] + ba1;
                float g0 = accg[mt][i][half * 2 + 0] + bg0;
                float g1 = accg[mt][i][half * 2 + 1] + bg1;
                float2 hres = *(const float2*)&g_zr[m * HH + cbase];
                if (apply_ln) {
                    float2 st = g_lnstat[m];
                    hres.x = (hres.x - st.x) * st.y * ga0 + be0;
                    hres.y = (hres.y - st.x) * st.y * ga1 + be1;
                }
                float2 zo;
                zo.x = a0 / (1.0f + expf(-g0)) + hres.x;
                zo.y = a1 / (1.0f + expf(-g1)) + hres.y;
                *(float2*)&g_zr[m * HH + cbase] = zo;
            }
        }
    }
}

// ---------------------------------------------------------------------------
// Pool phase 1: partial sums of LN(zr) over 128-row segments.
// ---------------------------------------------------------------------------
__global__ __launch_bounds__(256) void pool1_kernel(
        const float* __restrict__ lng3, const float* __restrict__ lnb3) {
    int b = blockIdx.x, seg = blockIdx.y, ch = threadIdx.x;
    size_t row0 = (size_t)b * LL + (size_t)seg * 128;
    const float* Hp = g_zr + row0 * HH + ch;
    const float2* stp = g_lnstat + row0;
    float ga = lng3[ch], be = lnb3[ch];
    float s = 0.f;
    for (int l = 0; l < 128; l++) {
        float2 st = stp[l];
        s += (Hp[(size_t)l * HH] - st.x) * st.y * ga + be;
    }
    g_poolp[(b * 16 + seg) * HH + ch] = s;
}

// ---------------------------------------------------------------------------
// Decoder MLP (fused pool finish): 256 -> 128 relu -> 64 relu -> 32
// ---------------------------------------------------------------------------
__global__ __launch_bounds__(128) void decoder_kernel(
        const float* __restrict__ w1, const float* __restrict__ b1,
        const float* __restrict__ w2, const float* __restrict__ b2,
        const float* __restrict__ w3, const float* __restrict__ b3,
        float* __restrict__ out) {
    __shared__ float p[HH];
    __shared__ float q1[DM1];
    __shared__ float q2[DM2];
    int b = blockIdx.x, tid = threadIdx.x;
    {
        float s0 = 0.f, s1 = 0.f;
        #pragma unroll
        for (int seg = 0; seg < 16; seg++) {
            s0 += g_poolp[(b * 16 + seg) * HH + tid];
            s1 += g_poolp[(b * 16 + seg) * HH + tid + 128];
        }
        p[tid]       = s0 * (1.0f / LL);
        p[tid + 128] = s1 * (1.0f / LL);
    }
    __syncthreads();
    {
        float s = b1[tid];
        #pragma unroll 4
        for (int k = 0; k < HH; k++) s = fmaf(p[k], w1[k * DM1 + tid], s);
        q1[tid] = fmaxf(s, 0.0f);
    }
    __syncthreads();
    if (tid < DM2) {
        float s = b2[tid];
        #pragma unroll 4
        for (int k = 0; k < DM1; k++) s = fmaf(q1[k], w2[k * DM2 + tid], s);
        q2[tid] = fmaxf(s, 0.0f);
    }
    __syncthreads();
    if (tid < DOUT) {
        float s = b3[tid];
        #pragma unroll 4
        for (int k = 0; k < DM2; k++) s = fmaf(q2[k], w3[k * DOUT + tid], s);
        out[b * DOUT + tid] = s;
    }
}

// ---------------------------------------------------------------------------
extern "C" void kernel_launch(void* const* d_in, const int* in_sizes, int n_in,
                              void* d_out, int out_size) {
    const float* x          = (const float*)d_in[0];
    const float* enc_w      = (const float*)d_in[1];
    const float* enc_b      = (const float*)d_in[2];
    const float* log_dt     = (const float*)d_in[3];
    const float* C_re       = (const float*)d_in[4];
    const float* C_im       = (const float*)d_in[5];
    const float* log_A_real = (const float*)d_in[6];
    const float* A_imag     = (const float*)d_in[7];
    const float* D_skip     = (const float*)d_in[8];
    const float* w_out      = (const float*)d_in[9];
    const float* b_out      = (const float*)d_in[10];
    const float* ln_g       = (const float*)d_in[11];
    const float* ln_b       = (const float*)d_in[12];
    const float* dec_w1     = (const float*)d_in[13];
    const float* dec_b1     = (const float*)d_in[14];
    const float* dec_w2     = (const float*)d_in[15];
    const float* dec_b2     = (const float*)d_in[16];
    const float* dec_w3     = (const float*)d_in[17];
    const float* dec_b3     = (const float*)d_in[18];
    float* out = (float*)d_out;

    cudaFuncSetAttribute(gemm_glu_tc,
                         cudaFuncAttributeMaxDynamicSharedMemorySize, GEMM_SMEM);

    prep_ctab_kernel<<<NLAYERS * HH * 16 / 128, 128>>>(log_dt, C_re, C_im,
                                                       log_A_real, A_imag);
    prep_w_kernel<<<(NLAYERS * 512 * 128 + 255) / 256, 256>>>(w_out);
    dim3 enc_grid(MROWS / 64, HH / 64);
    encoder_kernel<<<enc_grid, 256>>>(x, enc_w, enc_b);
    dim3 p1_grid(BB, HH / 16, NCHUNK - 1);
    dim3 p2_grid(BB, HH / 16, NCHUNK);
    for (int layer = 0; layer < NLAYERS; layer++) {
        int apply = (layer > 0) ? 1 : 0;
        const float* lgp = ln_g + (layer > 0 ? (layer - 1) * HH : 0);
        const float* lbp = ln_b + (layer > 0 ? (layer - 1) * HH : 0);
        scan_p1<<<p1_grid, 128>>>(lgp, lbp, apply, layer);
        scan_p2<<<p2_grid, 128>>>(D_skip, lgp, lbp, apply, layer);
        gemm_glu_tc<<<dim3(NMBLK, 4), 256, GEMM_SMEM>>>(b_out, lgp, lbp,
                                                        apply, layer);
        lnstat_kernel<<<MROWS / 8, 256>>>();
    }
    pool1_kernel<<<dim3(BB, 16), 256>>>(ln_g + 3 * HH, ln_b + 3 * HH);
    decoder_kernel<<<BB, 128>>>(dec_w1, dec_b1, dec_w2, dec_b2, dec_w3, dec_b3, out);
}

// round 16
// speedup vs baseline: 1.0770x; 1.0770x over previous
#include <cuda_runtime.h>
#include <cuda_bf16.h>
#include <cstdint>
#include <math.h>

#define BB 16
#define LL 2048
#define DIN 64
#define HH 256
#define NH 32
#define NLAYERS 4
#define DM1 128
#define DM2 64
#define DOUT 32

#define MROWS (BB*LL)          // 32768
#define NMBLK (MROWS/128)      // 256 row blocks

#define NCHUNK 16
#define CLEN (LL/NCHUNK)       // 128

typedef unsigned long long u64;

// Scratch (allocation-free contract: __device__ globals)
__device__ float g_zr [MROWS*HH];                // layer activations (pre-LN)
__device__ float2 g_lnstat[MROWS];               // per-row (mean, rstd)
// A fragments (bf16 pairs): [mblock(256)][kchunk(8)][ks(2)][mtile(8)][lane(32)][reg(4)]
__device__ __align__(16) uint32_t g_af_hi[(size_t)NMBLK*16384];
__device__ __align__(16) uint32_t g_af_lo[(size_t)NMBLK*16384];
// B fragments interleaved (hi0,lo0,hi1,lo1 per (nt,lane)):
__device__ __align__(16) uint32_t g_wf[(size_t)NLAYERS*4*32768];
// scan carries: [chunk][b][ch][state] complex  (chunk end-states from p1)
__device__ float2 g_carry[(size_t)NCHUNK*BB*HH*NH];
__device__ float g_poolp[BB*16*HH];

// ---------------------------------------------------------------------------
// helpers
// ---------------------------------------------------------------------------
__device__ __forceinline__ uint32_t smem_u32(const void* p) {
    uint32_t a;
    asm("{ .reg .u64 t; cvta.to.shared.u64 t, %1; cvt.u32.u64 %0, t; }"
        : "=r"(a) : "l"(p));
    return a;
}
__device__ __forceinline__ unsigned short bfu(float x) {
    return __bfloat16_as_ushort(__float2bfloat16_rn(x));
}
__device__ __forceinline__ float bff(unsigned short u) {
    return __bfloat162float(__ushort_as_bfloat16(u));
}
__device__ __forceinline__ void cp16(uint32_t dst, const void* src) {
    asm volatile("cp.async.cg.shared.global [%0], [%1], 16;"
                 :: "r"(dst), "l"(src));
}
__device__ __forceinline__ void mma_bf16(float* d, const uint32_t* a,
                                         uint32_t b0, uint32_t b1) {
    asm volatile(
        "mma.sync.aligned.m16n8k16.row.col.f32.bf16.bf16.f32 "
        "{%0,%1,%2,%3}, {%4,%5,%6,%7}, {%8,%9}, {%0,%1,%2,%3};"
        : "+f"(d[0]), "+f"(d[1]), "+f"(d[2]), "+f"(d[3])
        : "r"(a[0]), "r"(a[1]), "r"(a[2]), "r"(a[3]), "r"(b0), "r"(b1));
}
__device__ __forceinline__ u64 pk2(float lo, float hi) {
    u64 r; asm("mov.b64 %0, {%1, %2};" : "=l"(r) : "f"(lo), "f"(hi)); return r;
}
__device__ __forceinline__ void upk2(float& lo, float& hi, u64 v) {
    asm("mov.b64 {%0, %1}, %2;" : "=f"(lo), "=f"(hi) : "l"(v));
}
__device__ __forceinline__ u64 fma2(u64 a, u64 b, u64 c) {
    u64 d; asm("fma.rn.f32x2 %0, %1, %2, %3;" : "=l"(d) : "l"(a), "l"(b), "l"(c));
    return d;
}

// ---------------------------------------------------------------------------
// Weight prep: bf16x3 split of w_out into interleaved fragment order.
// ---------------------------------------------------------------------------
__global__ __launch_bounds__(256) void prep_w_kernel(const float* __restrict__ w) {
    int i = blockIdx.x * 256 + threadIdx.x;
    if (i >= NLAYERS * 512 * 128) return;
    int hp = i & 127;          int h = hp * 2;
    int o  = (i >> 7) & 511;
    int layer = i >> 16;
    float v0 = w[((size_t)(layer * 512) + o) * 256 + h];
    float v1 = w[((size_t)(layer * 512) + o) * 256 + h + 1];
    unsigned short h0 = bfu(v0), h1 = bfu(v1);
    unsigned short l0 = bfu(v0 - bff(h0)), l1 = bfu(v1 - bff(h1));
    int half = o >> 8;
    int nb   = (o & 255) >> 6;
    int nt   = ((o >> 3) & 7) | (half << 3);
    int gid  = o & 7;
    int kchunk = h >> 5;
    int ks   = (h >> 4) & 1;
    int kk   = h & 15;
    int tig  = (kk & 7) >> 1;
    int reg  = kk >> 3;
    int lane = gid * 4 + tig;
    size_t idx = ((((((size_t)(layer * 4 + nb) * 8 + kchunk) * 2 + ks) * 16 + nt) * 32 + lane) * 2 + reg) * 2;
    g_wf[idx]     = (uint32_t)h0 | ((uint32_t)h1 << 16);
    g_wf[idx + 1] = (uint32_t)l0 | ((uint32_t)l1 << 16);
}

// ---------------------------------------------------------------------------
// Encoder: g_zr[m, n] = x[m, :64] @ enc_w[:, n] + enc_b[n]
// ---------------------------------------------------------------------------
__global__ __launch_bounds__(256) void encoder_kernel(
        const float* __restrict__ X, const float* __restrict__ W,
        const float* __restrict__ bias) {
    __shared__ float As[64][36];
    __shared__ float Bs[32][68];
    int row0 = blockIdx.x * 64;
    int n0   = blockIdx.y * 64;
    int tid = threadIdx.x;
    int tx = tid & 15, ty = tid >> 4;
    float acc[4][4] = {};
    for (int k0 = 0; k0 < DIN; k0 += 32) {
        #pragma unroll
        for (int p = 0; p < 2; p++) {
            int q = tid + p * 256;
            int r = q >> 3, kq = q & 7;
            float4 v = *(const float4*)&X[(row0 + r) * DIN + k0 + kq * 4];
            *(float4*)&As[r][kq * 4] = v;
        }
        #pragma unroll
        for (int p = 0; p < 2; p++) {
            int q = tid + p * 256;
            int kk = q >> 4, nq = q & 15;
            float4 v = *(const float4*)&W[(k0 + kk) * HH + n0 + nq * 4];
            *(float4*)&Bs[kk][nq * 4] = v;
        }
        __syncthreads();
        #pragma unroll
        for (int k = 0; k < 32; k++) {
            float a[4];
            #pragma unroll
            for (int i = 0; i < 4; i++) a[i] = As[ty * 4 + i][k];
            float4 bv = *(const float4*)&Bs[k][tx * 4];
            float bj[4] = {bv.x, bv.y, bv.z, bv.w};
            #pragma unroll
            for (int i = 0; i < 4; i++)
                #pragma unroll
                for (int j = 0; j < 4; j++)
                    acc[i][j] = fmaf(a[i], bj[j], acc[i][j]);
        }
        __syncthreads();
    }
    #pragma unroll
    for (int i = 0; i < 4; i++) {
        int m = row0 + ty * 4 + i;
        #pragma unroll
        for (int j = 0; j < 4; j++) {
            int n = n0 + tx * 4 + j;
            g_zr[m * HH + n] = acc[i][j] + bias[n];
        }
    }
}

// ---------------------------------------------------------------------------
// LN stats: per-row mean/rstd of g_zr.  One warp per row.
// ---------------------------------------------------------------------------
__global__ __launch_bounds__(256) void lnstat_kernel() {
    int row  = blockIdx.x * 8 + (threadIdx.x >> 5);
    int lane = threadIdx.x & 31;
    const float* Z = g_zr + (size_t)row * HH;
    float4 v0 = *(const float4*)&Z[lane * 4];
    float4 v1 = *(const float4*)&Z[128 + lane * 4];
    float s  = v0.x + v0.y + v0.z + v0.w + v1.x + v1.y + v1.z + v1.w;
    float ss = v0.x*v0.x + v0.y*v0.y + v0.z*v0.z + v0.w*v0.w
             + v1.x*v1.x + v1.y*v1.y + v1.z*v1.z + v1.w*v1.w;
    #pragma unroll
    for (int o = 16; o; o >>= 1) {
        s  += __shfl_xor_sync(0xffffffffu, s,  o);
        ss += __shfl_xor_sync(0xffffffffu, ss, o);
    }
    float mean = s * (1.0f / 256.0f);
    float var  = ss * (1.0f / 256.0f) - mean * mean;
    if (lane == 0)
        g_lnstat[row] = make_float2(mean, rsqrtf(var + 1e-5f));
}

// ---------------------------------------------------------------------------
// Scan phase 1: per-chunk local recurrence (LN applied at tile load).
// grid (B, H/16, NCHUNK-1), block 128.
// ---------------------------------------------------------------------------
__global__ __launch_bounds__(128, 12) void scan_p1(
        const float* __restrict__ log_dt, const float* __restrict__ log_A_real,
        const float* __restrict__ A_imag,
        const float* __restrict__ lng_p, const float* __restrict__ lnb_p,
        int apply_ln, int layer) {
    __shared__ float s_in[128 * 16];
    int b   = blockIdx.x;
    int ch0 = blockIdx.y * 16;
    int chunk = blockIdx.z;
    int tid = threadIdx.x;
    int warp = tid >> 5, lane = tid & 31;
    int g = lane >> 3, j = lane & 7;
    int c_local = warp * 4 + g;
    int ch = ch0 + c_local;

    float dt = expf(log_dt[layer * HH + ch]);
    float wr[4], wi[4];
    #pragma unroll
    for (int k = 0; k < 4; k++) {
        int n = j * 4 + k;
        int idx = (layer * HH + ch) * NH + n;
        float Are = -expf(log_A_real[idx]);
        float Aim = A_imag[idx];
        float er  = expf(dt * Are);
        wr[k] = er * cosf(dt * Aim);
        wi[k] = er * sinf(dt * Aim);
    }
    u64 wre2[2], wim2[2], nwim2[2], sre2[2], sim2[2];
    #pragma unroll
    for (int g2 = 0; g2 < 2; g2++) {
        wre2[g2]  = pk2(wr[g2 * 2], wr[g2 * 2 + 1]);
        wim2[g2]  = pk2(wi[g2 * 2], wi[g2 * 2 + 1]);
        nwim2[g2] = pk2(-wi[g2 * 2], -wi[g2 * 2 + 1]);
        sre2[g2] = 0ull; sim2[g2] = 0ull;
    }

    size_t base_m = (size_t)b * LL + (size_t)chunk * CLEN;
    const float* hin = g_zr + base_m * HH;
    const float2* stp = g_lnstat + base_m;
    #pragma unroll
    for (int p = 0; p < 4; p++) {
        int q = tid + p * 128;
        int t = q >> 2, cq = q & 3;
        float4 v = *(const float4*)&hin[t * HH + ch0 + cq * 4];
        if (apply_ln) {
            float2 st = stp[t];
            float4 gg = *(const float4*)&lng_p[ch0 + cq * 4];
            float4 bb = *(const float4*)&lnb_p[ch0 + cq * 4];
            v.x = (v.x - st.x) * st.y * gg.x + bb.x;
            v.y = (v.y - st.x) * st.y * gg.y + bb.y;
            v.z = (v.z - st.x) * st.y * gg.z + bb.z;
            v.w = (v.w - st.x) * st.y * gg.w + bb.w;
        }
        *(float4*)&s_in[t * 16 + cq * 4] = v;
    }
    __syncthreads();
    #pragma unroll 8
    for (int t = 0; t < CLEN; t++) {
        float u = s_in[t * 16 + c_local];
        u64 u2 = pk2(u, u);
        #pragma unroll
        for (int g2 = 0; g2 < 2; g2++) {
            u64 nr = fma2(wre2[g2], sre2[g2], u2);
            nr = fma2(nwim2[g2], sim2[g2], nr);
            u64 ni = fma2(wre2[g2], sim2[g2], 0ull);
            ni = fma2(wim2[g2], sre2[g2], ni);
            sre2[g2] = nr; sim2[g2] = ni;
        }
    }
    size_t cbase = ((size_t)(chunk * BB + b) * HH + ch) * NH + j * 4;
    #pragma unroll
    for (int g2 = 0; g2 < 2; g2++) {
        float r0, r1, i0, i1;
        upk2(r0, r1, sre2[g2]);
        upk2(i0, i1, sim2[g2]);
        g_carry[cbase + g2 * 2 + 0] = make_float2(r0, i0);
        g_carry[cbase + g2 * 2 + 1] = make_float2(r1, i1);
    }
}

// ---------------------------------------------------------------------------
// Scan phase 2: carry combine (Horner) + per-chunk scan with 8-step batched
// butterfly reduction + D-skip + GELU + bf16x3 fragment emission.
// grid (B, H/16, NCHUNK), block 128.
// ---------------------------------------------------------------------------
__global__ __launch_bounds__(128, 10) void scan_p2(
        const float* __restrict__ log_dt, const float* __restrict__ C_re,
        const float* __restrict__ C_im,   const float* __restrict__ log_A_real,
        const float* __restrict__ A_imag, const float* __restrict__ D_skip,
        const float* __restrict__ lng_p, const float* __restrict__ lnb_p,
        int apply_ln, int layer) {
    __shared__ float s_buf[128 * 16];        // 8KB: input tile / scan output
    __shared__ uint32_t s_frag[2048];        // 8KB: hi (1024) | lo (1024)
    int b   = blockIdx.x;
    int ch0 = blockIdx.y * 16;
    int chunk = blockIdx.z;
    int tid = threadIdx.x;
    int warp = tid >> 5, lane = tid & 31;
    int g = lane >> 3, j = lane & 7;
    int c_local = warp * 4 + g;
    int ch = ch0 + c_local;

    float dsk = D_skip[layer * HH + ch];
    float dt  = expf(log_dt[layer * HH + ch]);
    float wr[4], wi[4], cr[4], ci[4], wpr[4], wpi[4], sr[4], si[4];
    #pragma unroll
    for (int k = 0; k < 4; k++) {
        int n = j * 4 + k;
        int idx = (layer * HH + ch) * NH + n;
        float Are = -expf(log_A_real[idx]);
        float Aim = A_imag[idx];
        float er  = expf(dt * Aim * 0.0f + dt * Are);   // er = exp(dt*Are)
        float wre = er * cosf(dt * Aim);
        float wim = er * sinf(dt * Aim);
        wr[k] = wre; wi[k] = wim;
        float nre = wre - 1.0f, nim = wim;
        float inv = 1.0f / (Are * Are + Aim * Aim);
        float ire = Are * inv, iim = -Aim * inv;
        float tre = nre * ire - nim * iim;
        float tim = nre * iim + nim * ire;
        float cre = C_re[idx], cim = C_im[idx];
        cr[k] = 2.0f * (cre * tre - cim * tim);
        ci[k] = 2.0f * (cre * tim + cim * tre);
        float erp = expf((float)CLEN * dt * Are);
        float angp = (float)CLEN * dt * Aim;
        wpr[k] = erp * cosf(angp);
        wpi[k] = erp * sinf(angp);
        sr[k] = 0.0f; si[k] = 0.0f;
    }
    // Horner combine of preceding chunk end-states -> true start state
    for (int c = 0; c < chunk; c++) {
        size_t cb = ((size_t)(c * BB + b) * HH + ch) * NH + j * 4;
        #pragma unroll
        for (int k = 0; k < 4; k++) {
            float2 e = g_carry[cb + k];
            float nr = wpr[k] * sr[k] - wpi[k] * si[k] + e.x;
            float ni = wpr[k] * si[k] + wpi[k] * sr[k] + e.y;
            sr[k] = nr; si[k] = ni;
        }
    }
    u64 wre2[2], wim2[2], nwim2[2], ckre2[2], nckim2[2], sre2[2], sim2[2];
    #pragma unroll
    for (int g2 = 0; g2 < 2; g2++) {
        wre2[g2]   = pk2(wr[g2 * 2], wr[g2 * 2 + 1]);
        wim2[g2]   = pk2(wi[g2 * 2], wi[g2 * 2 + 1]);
        nwim2[g2]  = pk2(-wi[g2 * 2], -wi[g2 * 2 + 1]);
        ckre2[g2]  = pk2(cr[g2 * 2], cr[g2 * 2 + 1]);
        nckim2[g2] = pk2(-ci[g2 * 2], -ci[g2 * 2 + 1]);
        sre2[g2]   = pk2(sr[g2 * 2], sr[g2 * 2 + 1]);
        sim2[g2]   = pk2(si[g2 * 2], si[g2 * 2 + 1]);
    }

    size_t base_m = (size_t)b * LL + (size_t)chunk * CLEN;
    const float* hin = g_zr + base_m * HH;
    const float2* stp = g_lnstat + base_m;

    #pragma unroll
    for (int p = 0; p < 4; p++) {
        int q = tid + p * 128;
        int t = q >> 2, cq = q & 3;
        float4 v = *(const float4*)&hin[t * HH + ch0 + cq * 4];
        if (apply_ln) {
            float2 st = stp[t];
            float4 gg = *(const float4*)&lng_p[ch0 + cq * 4];
            float4 bb = *(const float4*)&lnb_p[ch0 + cq * 4];
            v.x = (v.x - st.x) * st.y * gg.x + bb.x;
            v.y = (v.y - st.x) * st.y * gg.y + bb.y;
            v.z = (v.z - st.x) * st.y * gg.z + bb.z;
            v.w = (v.w - st.x) * st.y * gg.w + bb.w;
        }
        *(float4*)&s_buf[t * 16 + cq * 4] = v;
    }
    __syncthreads();
    // scan with 8-step batched butterfly; lane j owns t0+j; in-place writes
    // happen after all 8 reads in the group (warp-synchronous safe).
    int b0 = j & 1, b1 = (j >> 1) & 1, b2 = (j >> 2) & 1;
    for (int t0 = 0; t0 < CLEN; t0 += 8) {
        float q8[8];
        #pragma unroll
        for (int tt = 0; tt < 8; tt++) {
            float u = s_buf[(t0 + tt) * 16 + c_local];
            u64 u2 = pk2(u, u);
            u64 pacc2 = 0ull;
            #pragma unroll
            for (int g2 = 0; g2 < 2; g2++) {
                u64 nr = fma2(wre2[g2], sre2[g2], u2);
                nr = fma2(nwim2[g2], sim2[g2], nr);
                u64 ni = fma2(wre2[g2], sim2[g2], 0ull);
                ni = fma2(wim2[g2], sre2[g2], ni);
                sre2[g2] = nr; sim2[g2] = ni;
                pacc2 = fma2(ckre2[g2], nr, pacc2);
                pacc2 = fma2(nckim2[g2], ni, pacc2);
            }
            float pa, pb;
            upk2(pa, pb, pacc2);
            q8[tt] = pa + pb;
        }
        float r4[4];
        #pragma unroll
        for (int i2 = 0; i2 < 4; i2++) {
            float keep = b0 ? q8[2 * i2 + 1] : q8[2 * i2];
            float send = b0 ? q8[2 * i2]     : q8[2 * i2 + 1];
            r4[i2] = keep + __shfl_xor_sync(0xffffffffu, send, 1);
        }
        float r2[2];
        #pragma unroll
        for (int i2 = 0; i2 < 2; i2++) {
            float keep = b1 ? r4[2 * i2 + 1] : r4[2 * i2];
            float send = b1 ? r4[2 * i2]     : r4[2 * i2 + 1];
            r2[i2] = keep + __shfl_xor_sync(0xffffffffu, send, 2);
        }
        float keep = b2 ? r2[1] : r2[0];
        float send = b2 ? r2[0] : r2[1];
        float r = keep + __shfl_xor_sync(0xffffffffu, send, 4);
        int tw = t0 + j;
        float uo = s_buf[tw * 16 + c_local];
        s_buf[tw * 16 + c_local] = fmaf(uo, dsk, r);
    }
    __syncthreads();
    // GELU + bf16x3 split -> fragment buffer
    uint32_t* s_fh = s_frag;
    uint32_t* s_fl = s_frag + 1024;
    #pragma unroll
    for (int p = 0; p < 4; p++) {
        int q = tid + p * 128;
        int t = q >> 2, cq = q & 3;
        float4 v = *(const float4*)&s_buf[t * 16 + cq * 4];
        v.x = 0.5f * v.x * (1.0f + erff(v.x * 0.70710678118654752f));
        v.y = 0.5f * v.y * (1.0f + erff(v.y * 0.70710678118654752f));
        v.z = 0.5f * v.z * (1.0f + erff(v.z * 0.70710678118654752f));
        v.w = 0.5f * v.w * (1.0f + erff(v.w * 0.70710678118654752f));
        int mtile  = t >> 4;
        int rowsel = (t >> 3) & 1;
        int gid    = t & 7;
        int kk     = cq * 4;
        int tig0   = (kk & 7) >> 1;
        int reg    = rowsel + ((kk >> 3) << 1);
        int base   = (mtile * 32 + gid * 4 + tig0) * 4 + reg;
        unsigned short hx = bfu(v.x), hy = bfu(v.y), hz = bfu(v.z), hw = bfu(v.w);
        unsigned short lx = bfu(v.x - bff(hx)), ly = bfu(v.y - bff(hy));
        unsigned short lz = bfu(v.z - bff(hz)), lw = bfu(v.w - bff(hw));
        s_fh[base]     = (uint32_t)hx | ((uint32_t)hy << 16);
        s_fh[base + 4] = (uint32_t)hz | ((uint32_t)hw << 16);
        s_fl[base]     = (uint32_t)lx | ((uint32_t)ly << 16);
        s_fl[base + 4] = (uint32_t)lz | ((uint32_t)lw << 16);
    }
    __syncthreads();
    int mblk   = (int)(base_m >> 7);
    int kchunk = ch0 >> 5;
    int ks     = (ch0 >> 4) & 1;
    size_t gb = (size_t)mblk * 16384 + (size_t)(kchunk * 2 + ks) * 1024;
    #pragma unroll
    for (int p = 0; p < 2; p++) {
        int i = (tid + p * 128) * 4;
        *(uint4*)&g_af_hi[gb + i] = *(const uint4*)&s_fh[i];
        *(uint4*)&g_af_lo[gb + i] = *(const uint4*)&s_fl[i];
    }
}

// ---------------------------------------------------------------------------
// bf16x3 warp-MMA GEMM (interleaved B), register-GLU epilogue with inline LN,
// 3-stage cp.async pipeline.  Writes zr in place.
// ---------------------------------------------------------------------------
#define GEMM_SMEM 98304
__global__ __launch_bounds__(256, 2) void gemm_glu_tc(
        const float* __restrict__ bias_all,
        const float* __restrict__ lng_p, const float* __restrict__ lnb_p,
        int apply_ln, int layer) {
    extern __shared__ uint32_t sm[];
    int tid = threadIdx.x, lane = tid & 31, wid = tid >> 5;
    int wm = wid & 3, wn = wid >> 2;
    int mb = blockIdx.x, nb = blockIdx.y;
    uint32_t sbase = smem_u32(sm);

    const uint32_t* Ah = g_af_hi + (size_t)mb * 16384;
    const uint32_t* Al = g_af_lo + (size_t)mb * 16384;
    const uint32_t* Bi = g_wf + (size_t)(layer * 4 + nb) * 32768;

    float acca[2][4][4] = {};
    float accg[2][4][4] = {};

    #pragma unroll
    for (int st = 0; st < 3; st++) {
        uint32_t db = sbase + st * 32768u;
        #pragma unroll
        for (int ii = 0; ii < 2; ii++) {
            int c = tid + ii * 256;
            cp16(db +         c * 16, Ah + (size_t)st * 2048 + c * 4);
            cp16(db + 8192u + c * 16, Al + (size_t)st * 2048 + c * 4);
        }
        #pragma unroll
        for (int ii = 0; ii < 4; ii++) {
            int c = tid + ii * 256;
            cp16(db + 16384u + c * 16, Bi + (size_t)st * 4096 + c * 4);
        }
        asm volatile("cp.async.commit_group;");
    }

    for (int kc = 0; kc < 8; kc++) {
        asm volatile("cp.async.wait_group 2;");
        __syncthreads();
        int stg = kc % 3;
        const uint32_t* sAh = sm + stg * 8192;
        const uint32_t* sAl = sAh + 2048;
        const uint32_t* sB  = sAh + 4096;
        #pragma unroll
        for (int ks = 0; ks < 2; ks++) {
            uint32_t ah[2][4], al[2][4];
            #pragma unroll
            for (int mt = 0; mt < 2; mt++) {
                int base = (ks * 8 + wm * 2 + mt) * 128 + lane * 4;
                uint4 qh = *(const uint4*)&sAh[base];
                uint4 ql = *(const uint4*)&sAl[base];
                ah[mt][0] = qh.x; ah[mt][1] = qh.y; ah[mt][2] = qh.z; ah[mt][3] = qh.w;
                al[mt][0] = ql.x; al[mt][1] = ql.y; al[mt][2] = ql.z; al[mt][3] = ql.w;
            }
            #pragma unroll
            for (int i = 0; i < 4; i++) {
                int bidx_a = ((ks * 16 +     wn * 4 + i) * 32 + lane) * 4;
                int bidx_g = ((ks * 16 + 8 + wn * 4 + i) * 32 + lane) * 4;
                uint4 qa = *(const uint4*)&sB[bidx_a];   // hi0,lo0,hi1,lo1
                uint4 qg = *(const uint4*)&sB[bidx_g];
                #pragma unroll
                for (int mt = 0; mt < 2; mt++) {
                    mma_bf16(acca[mt][i], ah[mt], qa.x, qa.z);
                    mma_bf16(acca[mt][i], al[mt], qa.x, qa.z);
                    mma_bf16(acca[mt][i], ah[mt], qa.y, qa.w);
                    mma_bf16(accg[mt][i], ah[mt], qg.x, qg.z);
                    mma_bf16(accg[mt][i], al[mt], qg.x, qg.z);
                    mma_bf16(accg[mt][i], ah[mt], qg.y, qg.w);
                }
            }
        }
        __syncthreads();
        if (kc < 5) {
            int st = kc + 3;
            uint32_t db = sbase + (st % 3) * 32768u;
            #pragma unroll
            for (int ii = 0; ii < 2; ii++) {
                int c = tid + ii * 256;
                cp16(db +         c * 16, Ah + (size_t)st * 2048 + c * 4);
                cp16(db + 8192u + c * 16, Al + (size_t)st * 2048 + c * 4);
            }
            #pragma unroll
            for (int ii = 0; ii < 4; ii++) {
                int c = tid + ii * 256;
                cp16(db + 16384u + c * 16, Bi + (size_t)st * 4096 + c * 4);
            }
            asm volatile("cp.async.commit_group;");
        } else {
            asm volatile("cp.async.commit_group;");
        }
    }

    // register epilogue: bias + GLU + residual(LN'd) -> g_zr (in place)
    const float* brow = bias_all + layer * 512;
    #pragma unroll
    for (int i = 0; i < 4; i++) {
        int cbase = nb * 64 + wn * 32 + i * 8 + (lane & 3) * 2;
        float ba0 = brow[cbase],       ba1 = brow[cbase + 1];
        float bg0 = brow[cbase + 256], bg1 = brow[cbase + 257];
        float ga0 = 1.f, ga1 = 1.f, be0 = 0.f, be1 = 0.f;
        if (apply_ln) {
            ga0 = lng_p[cbase]; ga1 = lng_p[cbase + 1];
            be0 = lnb_p[cbase]; be1 = lnb_p[cbase + 1];
        }
        #pragma unroll
        for (int mt = 0; mt < 2; mt++) {
            int r0 = mb * 128 + wm * 32 + mt * 16 + (lane >> 2);
            #pragma unroll
            for (int half = 0; half < 2; half++) {
                size_t m = (size_t)r0 + half * 8;
                float a0 = acca[mt][i][half * 2 + 0] + ba0;
                float a1 = acca[mt][i][half * 2 + 1] + ba1;
                float g0 = accg[mt][i][half * 2 + 0] + bg0;
                float g1 = accg[mt][i][half * 2 + 1] + bg1;
                float2 hres = *(const float2*)&g_zr[m * HH + cbase];
                if (apply_ln) {
                    float2 st = g_lnstat[m];
                    hres.x = (hres.x - st.x) * st.y * ga0 + be0;
                    hres.y = (hres.y - st.x) * st.y * ga1 + be1;
                }
                float2 zo;
                zo.x = a0 / (1.0f + expf(-g0)) + hres.x;
                zo.y = a1 / (1.0f + expf(-g1)) + hres.y;
                *(float2*)&g_zr[m * HH + cbase] = zo;
            }
        }
    }
}

// ---------------------------------------------------------------------------
// Pool phase 1: partial sums of LN(zr) over 128-row segments.
// ---------------------------------------------------------------------------
__global__ __launch_bounds__(256) void pool1_kernel(
        const float* __restrict__ lng3, const float* __restrict__ lnb3) {
    int b = blockIdx.x, seg = blockIdx.y, ch = threadIdx.x;
    size_t row0 = (size_t)b * LL + (size_t)seg * 128;
    const float* Hp = g_zr + row0 * HH + ch;
    const float2* stp = g_lnstat + row0;
    float ga = lng3[ch], be = lnb3[ch];
    float s = 0.f;
    for (int l = 0; l < 128; l++) {
        float2 st = stp[l];
        s += (Hp[(size_t)l * HH] - st.x) * st.y * ga + be;
    }
    g_poolp[(b * 16 + seg) * HH + ch] = s;
}

// ---------------------------------------------------------------------------
// Decoder MLP (fused pool finish): 256 -> 128 relu -> 64 relu -> 32
// ---------------------------------------------------------------------------
__global__ __launch_bounds__(128) void decoder_kernel(
        const float* __restrict__ w1, const float* __restrict__ b1,
        const float* __restrict__ w2, const float* __restrict__ b2,
        const float* __restrict__ w3, const float* __restrict__ b3,
        float* __restrict__ out) {
    __shared__ float p[HH];
    __shared__ float q1[DM1];
    __shared__ float q2[DM2];
    int b = blockIdx.x, tid = threadIdx.x;
    {
        float s0 = 0.f, s1 = 0.f;
        #pragma unroll
        for (int seg = 0; seg < 16; seg++) {
            s0 += g_poolp[(b * 16 + seg) * HH + tid];
            s1 += g_poolp[(b * 16 + seg) * HH + tid + 128];
        }
        p[tid]       = s0 * (1.0f / LL);
        p[tid + 128] = s1 * (1.0f / LL);
    }
    __syncthreads();
    {
        float s = b1[tid];
        #pragma unroll 4
        for (int k = 0; k < HH; k++) s = fmaf(p[k], w1[k * DM1 + tid], s);
        q1[tid] = fmaxf(s, 0.0f);
    }
    __syncthreads();
    if (tid < DM2) {
        float s = b2[tid];
        #pragma unroll 4
        for (int k = 0; k < DM1; k++) s = fmaf(q1[k], w2[k * DM2 + tid], s);
        q2[tid] = fmaxf(s, 0.0f);
    }
    __syncthreads();
    if (tid < DOUT) {
        float s = b3[tid];
        #pragma unroll 4
        for (int k = 0; k < DM2; k++) s = fmaf(q2[k], w3[k * DOUT + tid], s);
        out[b * DOUT + tid] = s;
    }
}

// ---------------------------------------------------------------------------
extern "C" void kernel_launch(void* const* d_in, const int* in_sizes, int n_in,
                              void* d_out, int out_size) {
    const float* x          = (const float*)d_in[0];
    const float* enc_w      = (const float*)d_in[1];
    const float* enc_b      = (const float*)d_in[2];
    const float* log_dt     = (const float*)d_in[3];
    const float* C_re       = (const float*)d_in[4];
    const float* C_im       = (const float*)d_in[5];
    const float* log_A_real = (const float*)d_in[6];
    const float* A_imag     = (const float*)d_in[7];
    const float* D_skip     = (const float*)d_in[8];
    const float* w_out      = (const float*)d_in[9];
    const float* b_out      = (const float*)d_in[10];
    const float* ln_g       = (const float*)d_in[11];
    const float* ln_b       = (const float*)d_in[12];
    const float* dec_w1     = (const float*)d_in[13];
    const float* dec_b1     = (const float*)d_in[14];
    const float* dec_w2     = (const float*)d_in[15];
    const float* dec_b2     = (const float*)d_in[16];
    const float* dec_w3     = (const float*)d_in[17];
    const float* dec_b3     = (const float*)d_in[18];
    float* out = (float*)d_out;

    cudaFuncSetAttribute(gemm_glu_tc,
                         cudaFuncAttributeMaxDynamicSharedMemorySize, GEMM_SMEM);

    prep_w_kernel<<<(NLAYERS * 512 * 128 + 255) / 256, 256>>>(w_out);
    dim3 enc_grid(MROWS / 64, HH / 64);
    encoder_kernel<<<enc_grid, 256>>>(x, enc_w, enc_b);
    dim3 p1_grid(BB, HH / 16, NCHUNK - 1);
    dim3 p2_grid(BB, HH / 16, NCHUNK);
    for (int layer = 0; layer < NLAYERS; layer++) {
        int apply = (layer > 0) ? 1 : 0;
        const float* lgp = ln_g + (layer > 0 ? (layer - 1) * HH : 0);
        const float* lbp = ln_b + (layer > 0 ? (layer - 1) * HH : 0);
        scan_p1<<<p1_grid, 128>>>(log_dt, log_A_real, A_imag,
                                  lgp, lbp, apply, layer);
        scan_p2<<<p2_grid, 128>>>(log_dt, C_re, C_im,
                                  log_A_real, A_imag, D_skip,
                                  lgp, lbp, apply, layer);
        gemm_glu_tc<<<dim3(NMBLK, 4), 256, GEMM_SMEM>>>(b_out, lgp, lbp,
                                                        apply, layer);
        lnstat_kernel<<<MROWS / 8, 256>>>();
    }
    pool1_kernel<<<dim3(BB, 16), 256>>>(ln_g + 3 * HH, ln_b + 3 * HH);
    decoder_kernel<<<BB, 128>>>(dec_w1, dec_b1, dec_w2, dec_b2, dec_w3, dec_b3, out);
}